// round 5
// baseline (speedup 1.0000x reference)
#include <cuda_runtime.h>
#include <cuda_bf16.h>
#include <cuda_fp16.h>
#include <cstdint>

// Problem dims
#define BB 1024
#define TT 512
#define DD 128
#define HH 256
#define CCLS 2
#define NROWS 8
#define NCTA (BB / NROWS)   // 128 CTAs
#define NTHR 512

// ---- weight scratch (device globals; no allocations allowed) ----
// Small matrices transposed, fp32: WdhT[128][256], WdxT[128][128], WhT[256][128],
// WfT[128][128], WcT[256][128]
#define OFF_WDH 0
#define OFF_WDX 32768
#define OFF_WH  49152
#define OFF_WF  81920
#define OFF_WC  98304
#define WT_SMALL 131072
__device__ float g_wt[WT_SMALL];
// Big matrices, fp16, k-pair packed: wih2[k2][n] u32 = (f16 W[2k2+1][n])<<16 | f16 W[2k2][n]
// wih2: [128][1024] (K=256: c_c rows then m rows), whh2: [128][1024] (K=256: h rows)
#define BOFF_WIH_U32 0
#define BOFF_WHH_U32 131072
__device__ uint32_t g_wtb_u[262144];
// Combined gate bias bih+bhh
__device__ float g_gb[4 * HH];

typedef unsigned long long u64;

__device__ __forceinline__ u64 ffma2(u64 a, u64 b, u64 c) {
    u64 d;
    asm("fma.rn.f32x2 %0, %1, %2, %3;" : "=l"(d) : "l"(a), "l"(b), "l"(c));
    return d;
}
__device__ __forceinline__ u64 dup2(float w) {
    u64 d; asm("mov.b64 %0, {%1, %1};" : "=l"(d) : "f"(w)); return d;
}
// unpack u32 of two fp16 -> two f32
__device__ __forceinline__ void h2_to_f2(uint32_t v, float& a, float& b) {
    asm("{\n\t.reg .b16 lo, hi;\n\tmov.b32 {lo, hi}, %2;\n\t"
        "cvt.f32.f16 %0, lo;\n\tcvt.f32.f16 %1, hi;\n\t}"
        : "=f"(a), "=f"(b) : "r"(v));
}
__device__ __forceinline__ void unpk(u64 v, float& lo, float& hi) {
    asm("mov.b64 {%0, %1}, %2;" : "=f"(lo), "=f"(hi) : "l"(v));
}
__device__ __forceinline__ float sigf(float x) { return 1.f / (1.f + __expf(-x)); }
__device__ __forceinline__ float tanh_fast(float x) { return 2.f / (1.f + __expf(-2.f * x)) - 1.f; }

// 4-column, 2-k inner block of the gates GEMM.
// a[0..3]: rows 0-7 of k; a[4..7]: rows 0-7 of k+1. wv = fp16 k-pairs for 4 cols.
__device__ __forceinline__ void gates4(const float* actbase, uint4 wv, u64 (&acc)[4][4]) {
    const u64* ap = (const u64*)actbase;
    u64 a[8];
    #pragma unroll
    for (int p = 0; p < 8; ++p) a[p] = ap[p];
    uint32_t w[4] = {wv.x, wv.y, wv.z, wv.w};
    #pragma unroll
    for (int c = 0; c < 4; ++c) {
        float w0, w1; h2_to_f2(w[c], w0, w1);
        u64 W0 = dup2(w0), W1 = dup2(w1);
        #pragma unroll
        for (int p = 0; p < 4; ++p) {
            acc[c][p] = ffma2(a[p], W0, acc[c][p]);
            acc[c][p] = ffma2(a[4 + p], W1, acc[c][p]);
        }
    }
}

// ---- fused prologue: transposes + fp16 pack + bias combine, ONE launch ----
#define PREP_TOTAL (131072 + 262144 + 1024)
__global__ void prep_kernel(const float* __restrict__ Wdh, const float* __restrict__ Wdx,
                            const float* __restrict__ Wh,  const float* __restrict__ Wf,
                            const float* __restrict__ Wc,  const float* __restrict__ Wih,
                            const float* __restrict__ Whh, const float* __restrict__ bih,
                            const float* __restrict__ bhh) {
    int idx = blockIdx.x * blockDim.x + threadIdx.x;
    if (idx >= PREP_TOTAL) return;
    if (idx < 32768) {                     // WdhT[128][256] <- Wdh[256][128]
        int k = idx >> 8, n = idx & 255;
        g_wt[OFF_WDH + idx] = Wdh[n * 128 + k];
    } else if (idx < 49152) {              // WdxT[128][128] <- Wdx[128][128]
        int i = idx - 32768, k = i >> 7, n = i & 127;
        g_wt[idx] = Wdx[n * 128 + k];
    } else if (idx < 81920) {              // WhT[256][128] <- Wh[128][256]
        int i = idx - 49152, k = i >> 7, n = i & 127;
        g_wt[idx] = Wh[n * 256 + k];
    } else if (idx < 98304) {              // WfT[128][128] <- Wf[128][128]
        int i = idx - 81920, k = i >> 7, n = i & 127;
        g_wt[idx] = Wf[n * 128 + k];
    } else if (idx < 131072) {             // WcT[256][128] <- Wc[128][256]
        int i = idx - 98304, k = i >> 7, n = i & 127;
        g_wt[idx] = Wc[n * 256 + k];
    } else if (idx < 131072 + 131072) {    // wih2[k2][n] fp16-pair <- Wih[1024][256]
        int i = idx - 131072, k2 = i >> 10, n = i & 1023;
        uint32_t lo = __half_as_ushort(__float2half_rn(Wih[n * 256 + 2 * k2]));
        uint32_t hi = __half_as_ushort(__float2half_rn(Wih[n * 256 + 2 * k2 + 1]));
        g_wtb_u[BOFF_WIH_U32 + i] = lo | (hi << 16);
    } else if (idx < 131072 + 262144) {    // whh2[k2][n] fp16-pair <- Whh[1024][256]
        int i = idx - 131072 - 131072, k2 = i >> 10, n = i & 1023;
        uint32_t lo = __half_as_ushort(__float2half_rn(Whh[n * 256 + 2 * k2]));
        uint32_t hi = __half_as_ushort(__float2half_rn(Whh[n * 256 + 2 * k2 + 1]));
        g_wtb_u[BOFF_WHH_U32 + i] = lo | (hi << 16);
    } else {                               // combined gate bias
        int i = idx - 131072 - 262144;
        g_gb[i] = bih[i] + bhh[i];
    }
}

// ---- persistent RITS scan. Each CTA owns 8 batch rows for all 512 steps. ----
// Activations row-interleaved in smem: arr[k*8 + r] -> LDS.128 gives packed f32x2 row pairs.
__global__ void __launch_bounds__(NTHR, 1) rits_kernel(
    const float* __restrict__ values, const int* __restrict__ masks, const float* __restrict__ deltas,
    const float* __restrict__ bdh, const float* __restrict__ bdx,
    const float* __restrict__ bh,  const float* __restrict__ bf_,
    const float* __restrict__ bc,
    const float* __restrict__ Wo,  const float* __restrict__ bo,
    float* __restrict__ out)
{
    extern __shared__ float smem[];
    float* hs  = smem;            // [H*8]
    float* cs  = hs  + 2048;      // [H*8]
    float* hd  = cs  + 2048;      // [H*8]
    float* xs  = hd  + 2048;      // [D*8]
    float* msa = xs  + 1024;      // [D*8]
    float* dsa = msa + 1024;      // [D*8]
    float* xh  = dsa + 1024;      // [D*8]
    float* gx  = xh  + 1024;      // [D*8]
    float* al  = gx  + 1024;      // [D*8]
    float* zh  = al  + 1024;      // [D*8]
    float* xcb = zh  + 1024;      // [D*8]
    float* ccs = xcb + 1024;      // [D*8]
    float* gtA = ccs + 1024;      // [4H*8] gates partial (Wih half, incl bias)
    float* gtB = gtA + 8192;      // [4H*8] gates partial (Whh half)

    const int j = threadIdx.x;
    const int rowbase = blockIdx.x * NROWS;
    const float* wt = g_wt;
    float* out_imp = out + BB * CCLS;

    for (int i = j; i < 2048; i += NTHR) { hs[i] = 0.f; cs[i] = 0.f; }

    // input prefetch registers (double-buffer in regs across steps)
    float pv[2], pm[2], pd[2];
    {
        const int base0 = rowbase * (TT * DD);
        #pragma unroll
        for (int i = 0; i < 2; ++i) {
            int idx = j + i * NTHR;
            int r = idx >> 7, k = idx & 127;
            int g = base0 + r * (TT * DD) + k;
            pv[i] = values[g]; pm[i] = (float)masks[g]; pd[i] = deltas[g];
        }
    }
    __syncthreads();

    for (int t = 0; t < TT; ++t) {
        // ---- phase 1: commit prefetched x, m, d to smem ----
        #pragma unroll
        for (int i = 0; i < 2; ++i) {
            int idx = j + i * NTHR;
            int r = idx >> 7, k = idx & 127;
            int si = k * 8 + r;
            xs[si] = pv[i]; msa[si] = pm[i]; dsa[si] = pd[i];
        }
        __syncthreads();

        // issue next step's input loads (consumed next iteration)
        if (t + 1 < TT) {
            const int base0 = rowbase * (TT * DD) + (t + 1) * DD;
            #pragma unroll
            for (int i = 0; i < 2; ++i) {
                int idx = j + i * NTHR;
                int r = idx >> 7, k = idx & 127;
                int g = base0 + r * (TT * DD) + k;
                pv[i] = values[g]; pm[i] = (float)masks[g]; pd[i] = deltas[g];
            }
        }

        // ---- phase 2: gamma_h + h decay (j<128: 2 cols x 8 rows) |
        //              gamma_x (128<=j<256: 1 col x 8 rows) ----
        if (j < 128) {
            const int n0 = j * 2;
            u64 acc[2][4];
            {
                u64 b0 = dup2(bdh[n0]), b1 = dup2(bdh[n0 + 1]);
                #pragma unroll
                for (int p = 0; p < 4; ++p) { acc[0][p] = b0; acc[1][p] = b1; }
            }
            #pragma unroll 4
            for (int k = 0; k < DD; ++k) {
                float2 wv = *(const float2*)&wt[OFF_WDH + k * HH + n0];
                u64 W0 = dup2(wv.x), W1 = dup2(wv.y);
                const u64* ap = (const u64*)&dsa[k * 8];
                u64 a0 = ap[0], a1 = ap[1], a2 = ap[2], a3 = ap[3];
                acc[0][0] = ffma2(a0, W0, acc[0][0]); acc[1][0] = ffma2(a0, W1, acc[1][0]);
                acc[0][1] = ffma2(a1, W0, acc[0][1]); acc[1][1] = ffma2(a1, W1, acc[1][1]);
                acc[0][2] = ffma2(a2, W0, acc[0][2]); acc[1][2] = ffma2(a2, W1, acc[1][2]);
                acc[0][3] = ffma2(a3, W0, acc[0][3]); acc[1][3] = ffma2(a3, W1, acc[1][3]);
            }
            #pragma unroll
            for (int c = 0; c < 2; ++c) {
                float v[8];
                unpk(acc[c][0], v[0], v[1]); unpk(acc[c][1], v[2], v[3]);
                unpk(acc[c][2], v[4], v[5]); unpk(acc[c][3], v[6], v[7]);
                const int n = n0 + c;
                #pragma unroll
                for (int r = 0; r < 8; ++r) {
                    float g = __expf(-fmaxf(v[r], 0.f));
                    hd[n * 8 + r] = hs[n * 8 + r] * g;
                }
            }
        } else if (j < 256) {
            const int n = j - 128;
            u64 a0 = dup2(bdx[n]), a1 = a0, a2 = a0, a3 = a0;
            #pragma unroll 4
            for (int k = 0; k < DD; ++k) {
                u64 wp = dup2(wt[OFF_WDX + k * DD + n]);
                const u64* ap = (const u64*)&dsa[k * 8];
                a0 = ffma2(ap[0], wp, a0); a1 = ffma2(ap[1], wp, a1);
                a2 = ffma2(ap[2], wp, a2); a3 = ffma2(ap[3], wp, a3);
            }
            float v[8];
            unpk(a0, v[0], v[1]); unpk(a1, v[2], v[3]);
            unpk(a2, v[4], v[5]); unpk(a3, v[6], v[7]);
            #pragma unroll
            for (int r = 0; r < 8; ++r) gx[n * 8 + r] = __expf(-fmaxf(v[r], 0.f));
        }
        __syncthreads();

        // ---- phase 3: x_h (j<64: 2 cols x 8 rows, K=256) |
        //              alpha (64<=j<128: 2 cols x 8 rows, K=256) ----
        if (j < 64) {
            const int n0 = j * 2;
            u64 acc[2][4];
            {
                u64 b0 = dup2(bh[n0]), b1 = dup2(bh[n0 + 1]);
                #pragma unroll
                for (int p = 0; p < 4; ++p) { acc[0][p] = b0; acc[1][p] = b1; }
            }
            #pragma unroll 4
            for (int k = 0; k < HH; ++k) {
                float2 wv = *(const float2*)&wt[OFF_WH + k * DD + n0];
                u64 W0 = dup2(wv.x), W1 = dup2(wv.y);
                const u64* ap = (const u64*)&hd[k * 8];
                u64 a0 = ap[0], a1 = ap[1], a2 = ap[2], a3 = ap[3];
                acc[0][0] = ffma2(a0, W0, acc[0][0]); acc[1][0] = ffma2(a0, W1, acc[1][0]);
                acc[0][1] = ffma2(a1, W0, acc[0][1]); acc[1][1] = ffma2(a1, W1, acc[1][1]);
                acc[0][2] = ffma2(a2, W0, acc[0][2]); acc[1][2] = ffma2(a2, W1, acc[1][2]);
                acc[0][3] = ffma2(a3, W0, acc[0][3]); acc[1][3] = ffma2(a3, W1, acc[1][3]);
            }
            #pragma unroll
            for (int c = 0; c < 2; ++c) {
                float v[8];
                unpk(acc[c][0], v[0], v[1]); unpk(acc[c][1], v[2], v[3]);
                unpk(acc[c][2], v[4], v[5]); unpk(acc[c][3], v[6], v[7]);
                *(float4*)&xh[(n0 + c) * 8]     = make_float4(v[0], v[1], v[2], v[3]);
                *(float4*)&xh[(n0 + c) * 8 + 4] = make_float4(v[4], v[5], v[6], v[7]);
            }
        } else if (j < 128) {
            const int n0 = (j - 64) * 2;
            u64 acc[2][4];
            {
                u64 b0 = dup2(bc[n0]), b1 = dup2(bc[n0 + 1]);
                #pragma unroll
                for (int p = 0; p < 4; ++p) { acc[0][p] = b0; acc[1][p] = b1; }
            }
            #pragma unroll 4
            for (int k = 0; k < DD; ++k) {
                float2 wv = *(const float2*)&wt[OFF_WC + k * DD + n0];
                u64 W0 = dup2(wv.x), W1 = dup2(wv.y);
                const u64* ap = (const u64*)&gx[k * 8];
                u64 a0 = ap[0], a1 = ap[1], a2 = ap[2], a3 = ap[3];
                acc[0][0] = ffma2(a0, W0, acc[0][0]); acc[1][0] = ffma2(a0, W1, acc[1][0]);
                acc[0][1] = ffma2(a1, W0, acc[0][1]); acc[1][1] = ffma2(a1, W1, acc[1][1]);
                acc[0][2] = ffma2(a2, W0, acc[0][2]); acc[1][2] = ffma2(a2, W1, acc[1][2]);
                acc[0][3] = ffma2(a3, W0, acc[0][3]); acc[1][3] = ffma2(a3, W1, acc[1][3]);
            }
            #pragma unroll 4
            for (int k = 0; k < DD; ++k) {
                float2 wv = *(const float2*)&wt[OFF_WC + (k + DD) * DD + n0];
                u64 W0 = dup2(wv.x), W1 = dup2(wv.y);
                const u64* ap = (const u64*)&msa[k * 8];
                u64 a0 = ap[0], a1 = ap[1], a2 = ap[2], a3 = ap[3];
                acc[0][0] = ffma2(a0, W0, acc[0][0]); acc[1][0] = ffma2(a0, W1, acc[1][0]);
                acc[0][1] = ffma2(a1, W0, acc[0][1]); acc[1][1] = ffma2(a1, W1, acc[1][1]);
                acc[0][2] = ffma2(a2, W0, acc[0][2]); acc[1][2] = ffma2(a2, W1, acc[1][2]);
                acc[0][3] = ffma2(a3, W0, acc[0][3]); acc[1][3] = ffma2(a3, W1, acc[1][3]);
            }
            #pragma unroll
            for (int c = 0; c < 2; ++c) {
                float v[8];
                unpk(acc[c][0], v[0], v[1]); unpk(acc[c][1], v[2], v[3]);
                unpk(acc[c][2], v[4], v[5]); unpk(acc[c][3], v[6], v[7]);
                *(float4*)&al[(n0 + c) * 8]     = make_float4(v[0], v[1], v[2], v[3]);
                *(float4*)&al[(n0 + c) * 8 + 4] = make_float4(v[4], v[5], v[6], v[7]);
            }
        }
        __syncthreads();

        // ---- phase 3.5: x_c = m*x + (1-m)*x_h ----
        #pragma unroll
        for (int i = 0; i < 2; ++i) {
            int idx = j + i * NTHR;
            float mv = msa[idx];
            xcb[idx] = mv * xs[idx] + (1.f - mv) * xh[idx];
        }
        __syncthreads();

        // ---- phase 4: z_h = x_c@Wf.T + bf (j<128: 1 col x 8 rows) ----
        if (j < 128) {
            const int n = j;
            u64 a0 = dup2(bf_[n]), a1 = a0, a2 = a0, a3 = a0;
            #pragma unroll 4
            for (int k = 0; k < DD; ++k) {
                u64 wp = dup2(wt[OFF_WF + k * DD + n]);
                const u64* ap = (const u64*)&xcb[k * 8];
                a0 = ffma2(ap[0], wp, a0); a1 = ffma2(ap[1], wp, a1);
                a2 = ffma2(ap[2], wp, a2); a3 = ffma2(ap[3], wp, a3);
            }
            float v[8];
            unpk(a0, v[0], v[1]); unpk(a1, v[2], v[3]);
            unpk(a2, v[4], v[5]); unpk(a3, v[6], v[7]);
            *(float4*)&zh[n * 8]     = make_float4(v[0], v[1], v[2], v[3]);
            *(float4*)&zh[n * 8 + 4] = make_float4(v[4], v[5], v[6], v[7]);
        }
        __syncthreads();

        // ---- phase 5: c_h, c_c; write imputation ----
        {
            const int base0 = rowbase * (TT * DD) + t * DD;
            #pragma unroll
            for (int i = 0; i < 2; ++i) {
                int idx2 = j + i * NTHR;
                int r = idx2 >> 7, k = idx2 & 127;
                int si = k * 8 + r;
                float a = al[si], zv = zh[si], xhv = xh[si], mv = msa[si], xv = xs[si];
                float ch = a * zv + (1.f - a) * xhv;
                float cc = mv * xv + (1.f - mv) * ch;
                ccs[si] = cc;
                out_imp[base0 + r * (TT * DD) + k] = cc;
            }
        }
        __syncthreads();

        // ---- phase 6: gates, K-split, 4 cols/thread ----
        // threads 0-255: Wih half (K=256 over [c_c, m]), bias included -> gtA
        // threads 256-511: Whh half (K=256 over hd) -> gtB
        {
            u64 acc[4][4];
            if (j < 256) {
                const int n0 = j << 2;
                #pragma unroll
                for (int c = 0; c < 4; ++c) {
                    u64 b = dup2(g_gb[n0 + c]);
                    #pragma unroll
                    for (int p = 0; p < 4; ++p) acc[c][p] = b;
                }
                const uint32_t* wih2 = g_wtb_u + BOFF_WIH_U32;
                #pragma unroll 2
                for (int k2 = 0; k2 < 64; ++k2) {
                    uint4 wv = *(const uint4*)&wih2[k2 * 1024 + n0];
                    gates4(&ccs[k2 * 16], wv, acc);
                }
                #pragma unroll 2
                for (int k2 = 0; k2 < 64; ++k2) {
                    uint4 wv = *(const uint4*)&wih2[(k2 + 64) * 1024 + n0];
                    gates4(&msa[k2 * 16], wv, acc);
                }
                #pragma unroll
                for (int c = 0; c < 4; ++c) {
                    float v[8];
                    unpk(acc[c][0], v[0], v[1]); unpk(acc[c][1], v[2], v[3]);
                    unpk(acc[c][2], v[4], v[5]); unpk(acc[c][3], v[6], v[7]);
                    *(float4*)&gtA[(n0 + c) * 8]     = make_float4(v[0], v[1], v[2], v[3]);
                    *(float4*)&gtA[(n0 + c) * 8 + 4] = make_float4(v[4], v[5], v[6], v[7]);
                }
            } else {
                const int n0 = (j - 256) << 2;
                u64 z = dup2(0.f);
                #pragma unroll
                for (int c = 0; c < 4; ++c)
                    #pragma unroll
                    for (int p = 0; p < 4; ++p) acc[c][p] = z;
                const uint32_t* whh2 = g_wtb_u + BOFF_WHH_U32;
                #pragma unroll 2
                for (int k2 = 0; k2 < 128; ++k2) {
                    uint4 wv = *(const uint4*)&whh2[k2 * 1024 + n0];
                    gates4(&hd[k2 * 16], wv, acc);
                }
                #pragma unroll
                for (int c = 0; c < 4; ++c) {
                    float v[8];
                    unpk(acc[c][0], v[0], v[1]); unpk(acc[c][1], v[2], v[3]);
                    unpk(acc[c][2], v[4], v[5]); unpk(acc[c][3], v[6], v[7]);
                    *(float4*)&gtB[(n0 + c) * 8]     = make_float4(v[0], v[1], v[2], v[3]);
                    *(float4*)&gtB[(n0 + c) * 8 + 4] = make_float4(v[4], v[5], v[6], v[7]);
                }
            }
        }
        __syncthreads();

        // ---- phase 7: LSTM cell update (2 threads per h-column, 4 rows each) ----
        {
            const int n = j & 255, half = j >> 8;
            #pragma unroll
            for (int r0 = 0; r0 < 4; ++r0) {
                int r = half * 4 + r0;
                float ig = sigf(gtA[n * 8 + r] + gtB[n * 8 + r]);
                float fg = sigf(gtA[(n + HH) * 8 + r] + gtB[(n + HH) * 8 + r]);
                float gg = tanh_fast(gtA[(n + 2 * HH) * 8 + r] + gtB[(n + 2 * HH) * 8 + r]);
                float og = sigf(gtA[(n + 3 * HH) * 8 + r] + gtB[(n + 3 * HH) * 8 + r]);
                float cn = fg * cs[n * 8 + r] + ig * gg;
                cs[n * 8 + r] = cn;
                hs[n * 8 + r] = og * tanh_fast(cn);
            }
        }
        __syncthreads();
    }

    // ---- final: y_h = h@Wo.T + bo ----
    if (j < NROWS * CCLS) {
        int r = j >> 1, cl = j & 1;
        float acc = bo[cl];
        #pragma unroll 8
        for (int k = 0; k < HH; ++k) acc += hs[k * 8 + r] * Wo[cl * HH + k];
        out[(rowbase + r) * CCLS + cl] = acc;
    }
}

extern "C" void kernel_launch(void* const* d_in, const int* in_sizes, int n_in,
                              void* d_out, int out_size) {
    const float* values = (const float*)d_in[0];
    const int*   masks  = (const int*)  d_in[1];
    const float* deltas = (const float*)d_in[2];
    const float* Wdh = (const float*)d_in[3];
    const float* bdh = (const float*)d_in[4];
    const float* Wdx = (const float*)d_in[5];
    const float* bdx = (const float*)d_in[6];
    const float* Wh  = (const float*)d_in[7];
    const float* bh  = (const float*)d_in[8];
    const float* Wf  = (const float*)d_in[9];
    const float* bf_ = (const float*)d_in[10];
    const float* Wc  = (const float*)d_in[11];
    const float* bc  = (const float*)d_in[12];
    const float* Wih = (const float*)d_in[13];
    const float* bih = (const float*)d_in[14];
    const float* Whh = (const float*)d_in[15];
    const float* bhh = (const float*)d_in[16];
    const float* Wo  = (const float*)d_in[17];
    const float* bo  = (const float*)d_in[18];
    float* out = (float*)d_out;

    prep_kernel<<<(PREP_TOTAL + 255) / 256, 256>>>(Wdh, Wdx, Wh, Wf, Wc, Wih, Whh, bih, bhh);

    size_t smem_bytes = 31744 * sizeof(float);  // 124 KB
    cudaFuncSetAttribute(rits_kernel, cudaFuncAttributeMaxDynamicSharedMemorySize,
                         (int)smem_bytes);
    rits_kernel<<<NCTA, NTHR, smem_bytes>>>(values, masks, deltas,
                                            bdh, bdx, bh, bf_, bc,
                                            Wo, bo, out);
}

// round 6
// speedup vs baseline: 1.5597x; 1.5597x over previous
#include <cuda_runtime.h>
#include <cuda_bf16.h>
#include <cuda_fp16.h>
#include <cstdint>

// Problem dims
#define BB 1024
#define TT 512
#define DD 128
#define HH 256
#define CCLS 2
#define NROWS 8
#define NCTA (BB / NROWS)   // 128 CTAs
#define NTHR 512

// ---- weight scratch (device globals; no allocations allowed) ----
// Small matrices transposed, fp32: WdhT[128][256], WdxT[128][128], WhT[256][128],
// WfT[128][128], WcT[256][128]
#define OFF_WDH 0
#define OFF_WDX 32768
#define OFF_WH  49152
#define OFF_WF  81920
#define OFF_WC  98304
#define WT_SMALL 131072
__device__ float g_wt[WT_SMALL];
// Gates weights, fp16, packed in mma.sync B-fragment order:
// u32 index i = ((((w*32 + s)*32 + t)*8 + u)*2 + j2)
//   w = warp (16), s = k-step (32), t = lane (32), u = n8 tile (8), j2 = b0/b1
//   k0 = s*16 + (t&3)*2 + j2*8,  n = w*64 + u*8 + (t>>2)
//   value = half2( W[k0][n], W[k0+1][n] ),  W[k][n] = k<256 ? Wih[n][k] : Whh[n][k-256]
__device__ uint32_t g_wtb_u[262144];
// Combined gate bias bih+bhh
__device__ float g_gb[4 * HH];

typedef unsigned long long u64;

__device__ __forceinline__ u64 ffma2(u64 a, u64 b, u64 c) {
    u64 d;
    asm("fma.rn.f32x2 %0, %1, %2, %3;" : "=l"(d) : "l"(a), "l"(b), "l"(c));
    return d;
}
__device__ __forceinline__ u64 dup2(float w) {
    u64 d; asm("mov.b64 %0, {%1, %1};" : "=l"(d) : "f"(w)); return d;
}
__device__ __forceinline__ void unpk(u64 v, float& lo, float& hi) {
    asm("mov.b64 {%0, %1}, %2;" : "=f"(lo), "=f"(hi) : "l"(v));
}
__device__ __forceinline__ float sigf(float x) { return 1.f / (1.f + __expf(-x)); }
__device__ __forceinline__ float tanh_fast(float x) { return 2.f / (1.f + __expf(-2.f * x)) - 1.f; }

// m16n8k16 HMMA; A rows 8-15 are zero (a1 = a3 = 0), c2/c3 are discarded lanes.
__device__ __forceinline__ void mma1(float& c0, float& c1, float& c2, float& c3,
                                     uint32_t a0, uint32_t a2, uint32_t b0, uint32_t b1) {
    asm volatile(
        "mma.sync.aligned.m16n8k16.row.col.f32.f16.f16.f32 "
        "{%0,%1,%2,%3}, {%4,%5,%6,%7}, {%8,%9}, {%0,%1,%2,%3};"
        : "+f"(c0), "+f"(c1), "+f"(c2), "+f"(c3)
        : "r"(a0), "r"(0u), "r"(a2), "r"(0u), "r"(b0), "r"(b1));
}

// ---- fused prologue: transposes + fragment packing + bias combine, ONE launch ----
#define PREP_TOTAL (131072 + 262144 + 1024)
__global__ void prep_kernel(const float* __restrict__ Wdh, const float* __restrict__ Wdx,
                            const float* __restrict__ Wh,  const float* __restrict__ Wf,
                            const float* __restrict__ Wc,  const float* __restrict__ Wih,
                            const float* __restrict__ Whh, const float* __restrict__ bih,
                            const float* __restrict__ bhh) {
    int idx = blockIdx.x * blockDim.x + threadIdx.x;
    if (idx >= PREP_TOTAL) return;
    if (idx < 32768) {                     // WdhT[128][256] <- Wdh[256][128]
        int k = idx >> 8, n = idx & 255;
        g_wt[OFF_WDH + idx] = Wdh[n * 128 + k];
    } else if (idx < 49152) {              // WdxT[128][128] <- Wdx[128][128]
        int i = idx - 32768, k = i >> 7, n = i & 127;
        g_wt[idx] = Wdx[n * 128 + k];
    } else if (idx < 81920) {              // WhT[256][128] <- Wh[128][256]
        int i = idx - 49152, k = i >> 7, n = i & 127;
        g_wt[idx] = Wh[n * 256 + k];
    } else if (idx < 98304) {              // WfT[128][128] <- Wf[128][128]
        int i = idx - 81920, k = i >> 7, n = i & 127;
        g_wt[idx] = Wf[n * 128 + k];
    } else if (idx < 131072) {             // WcT[256][128] <- Wc[128][256]
        int i = idx - 98304, k = i >> 7, n = i & 127;
        g_wt[idx] = Wc[n * 256 + k];
    } else if (idx < 131072 + 262144) {    // mma B-fragment pack
        int i = idx - 131072;
        int j2 = i & 1;
        int u  = (i >> 1) & 7;
        int t  = (i >> 4) & 31;
        int s  = (i >> 9) & 31;
        int w  = (i >> 14) & 15;
        int k0 = s * 16 + (t & 3) * 2 + j2 * 8;
        int n  = w * 64 + u * 8 + (t >> 2);
        float lo, hi;
        if (k0 < 256) { lo = Wih[n * 256 + k0];       hi = Wih[n * 256 + k0 + 1]; }
        else          { lo = Whh[n * 256 + k0 - 256]; hi = Whh[n * 256 + k0 - 255]; }
        uint32_t l = __half_as_ushort(__float2half_rn(lo));
        uint32_t h = __half_as_ushort(__float2half_rn(hi));
        g_wtb_u[i] = l | (h << 16);
    } else {                               // combined gate bias
        int i = idx - 131072 - 262144;
        g_gb[i] = bih[i] + bhh[i];
    }
}

// ---- persistent RITS scan. Each CTA owns 8 batch rows for all 512 steps. ----
// fp32 activations row-interleaved: arr[k*8 + r]. fp16 gates-input shadow:
// inpH[r][0:128)=c_c, [128:256)=m, [256:512)=hd, row pitch 520 halves.
#define INPH_PITCH 520
__global__ void __launch_bounds__(NTHR, 1) rits_kernel(
    const float* __restrict__ values, const int* __restrict__ masks, const float* __restrict__ deltas,
    const float* __restrict__ bdh, const float* __restrict__ bdx,
    const float* __restrict__ bh,  const float* __restrict__ bf_,
    const float* __restrict__ bc,
    const float* __restrict__ Wo,  const float* __restrict__ bo,
    float* __restrict__ out)
{
    extern __shared__ float smem[];
    float* hs  = smem;            // [H*8]
    float* cs  = hs  + 2048;      // [H*8]
    float* hd  = cs  + 2048;      // [H*8]
    float* xs  = hd  + 2048;      // [D*8]
    float* msa = xs  + 1024;      // [D*8]
    float* dsa = msa + 1024;      // [D*8]
    float* xh  = dsa + 1024;      // [D*8]
    float* gx  = xh  + 1024;      // [D*8]
    float* al  = gx  + 1024;      // [D*8]
    float* zh  = al  + 1024;      // [D*8]
    float* xcb = zh  + 1024;      // [D*8]
    float* gt  = xcb + 1024;      // [4H*8] gates (bias included)
    __half* inpH = (__half*)(gt + 8192);  // [8][520]

    const int j = threadIdx.x;
    const int rowbase = blockIdx.x * NROWS;
    const float* wt = g_wt;
    float* out_imp = out + BB * CCLS;

    for (int i = j; i < 2048; i += NTHR) { hs[i] = 0.f; cs[i] = 0.f; }

    // input prefetch registers (double-buffer in regs across steps)
    float pv[2], pm[2], pd[2];
    {
        const int base0 = rowbase * (TT * DD);
        #pragma unroll
        for (int i = 0; i < 2; ++i) {
            int idx = j + i * NTHR;
            int r = idx >> 7, k = idx & 127;
            int g = base0 + r * (TT * DD) + k;
            pv[i] = values[g]; pm[i] = (float)masks[g]; pd[i] = deltas[g];
        }
    }
    __syncthreads();

    for (int t = 0; t < TT; ++t) {
        // ---- phase 1: commit prefetched x, m, d to smem (+ fp16 m) ----
        #pragma unroll
        for (int i = 0; i < 2; ++i) {
            int idx = j + i * NTHR;
            int r = idx >> 7, k = idx & 127;
            int si = k * 8 + r;
            xs[si] = pv[i]; msa[si] = pm[i]; dsa[si] = pd[i];
            inpH[r * INPH_PITCH + 128 + k] = __float2half(pm[i]);
        }
        __syncthreads();

        // issue next step's input loads (consumed next iteration)
        if (t + 1 < TT) {
            const int base0 = rowbase * (TT * DD) + (t + 1) * DD;
            #pragma unroll
            for (int i = 0; i < 2; ++i) {
                int idx = j + i * NTHR;
                int r = idx >> 7, k = idx & 127;
                int g = base0 + r * (TT * DD) + k;
                pv[i] = values[g]; pm[i] = (float)masks[g]; pd[i] = deltas[g];
            }
        }

        // ---- phase 2: gamma_h + h decay (j<256, 1 col) | gamma_x (j>=256) ----
        if (j < 256) {
            const int n = j;
            u64 a0 = dup2(bdh[n]), a1 = a0, a2 = a0, a3 = a0;
            #pragma unroll 8
            for (int k = 0; k < DD; ++k) {
                u64 wp = dup2(wt[OFF_WDH + k * HH + n]);
                const u64* ap = (const u64*)&dsa[k * 8];
                a0 = ffma2(ap[0], wp, a0); a1 = ffma2(ap[1], wp, a1);
                a2 = ffma2(ap[2], wp, a2); a3 = ffma2(ap[3], wp, a3);
            }
            float v[8];
            unpk(a0, v[0], v[1]); unpk(a1, v[2], v[3]);
            unpk(a2, v[4], v[5]); unpk(a3, v[6], v[7]);
            #pragma unroll
            for (int r = 0; r < 8; ++r) {
                float g = __expf(-fmaxf(v[r], 0.f));
                float hv = hs[n * 8 + r] * g;
                hd[n * 8 + r] = hv;
                inpH[r * INPH_PITCH + 256 + n] = __float2half(hv);
            }
        } else {
            const int jj = j - 256;
            const int n = jj & 127, half = jj >> 7;       // 4 rows each
            u64 a0 = dup2(bdx[n]), a1 = a0;
            #pragma unroll 8
            for (int k = 0; k < DD; ++k) {
                u64 wp = dup2(wt[OFF_WDX + k * DD + n]);
                const u64* ap = (const u64*)&dsa[k * 8 + half * 4];
                a0 = ffma2(ap[0], wp, a0); a1 = ffma2(ap[1], wp, a1);
            }
            float v[4]; unpk(a0, v[0], v[1]); unpk(a1, v[2], v[3]);
            #pragma unroll
            for (int r = 0; r < 4; ++r) gx[n * 8 + half * 4 + r] = __expf(-fmaxf(v[r], 0.f));
        }
        __syncthreads();

        // ---- phase 3: x_h (j<256) | alpha (j>=256); 4 rows per thread ----
        if (j < 256) {
            const int n = j & 127, half = j >> 7;
            u64 a0 = dup2(bh[n]), a1 = a0;
            #pragma unroll 8
            for (int k = 0; k < HH; ++k) {
                u64 wp = dup2(wt[OFF_WH + k * DD + n]);
                const u64* ap = (const u64*)&hd[k * 8 + half * 4];
                a0 = ffma2(ap[0], wp, a0); a1 = ffma2(ap[1], wp, a1);
            }
            float v[4]; unpk(a0, v[0], v[1]); unpk(a1, v[2], v[3]);
            #pragma unroll
            for (int r = 0; r < 4; ++r) xh[n * 8 + half * 4 + r] = v[r];
        } else {
            const int jj = j - 256;
            const int n = jj & 127, half = jj >> 7;
            u64 a0 = dup2(bc[n]), a1 = a0;
            #pragma unroll 8
            for (int k = 0; k < DD; ++k) {
                u64 wp = dup2(wt[OFF_WC + k * DD + n]);
                const u64* ap = (const u64*)&gx[k * 8 + half * 4];
                a0 = ffma2(ap[0], wp, a0); a1 = ffma2(ap[1], wp, a1);
            }
            #pragma unroll 8
            for (int k = 0; k < DD; ++k) {
                u64 wp = dup2(wt[OFF_WC + (k + DD) * DD + n]);
                const u64* ap = (const u64*)&msa[k * 8 + half * 4];
                a0 = ffma2(ap[0], wp, a0); a1 = ffma2(ap[1], wp, a1);
            }
            float v[4]; unpk(a0, v[0], v[1]); unpk(a1, v[2], v[3]);
            #pragma unroll
            for (int r = 0; r < 4; ++r) al[n * 8 + half * 4 + r] = v[r];
        }
        __syncthreads();

        // ---- phase 3.5: x_c = m*x + (1-m)*x_h ----
        #pragma unroll
        for (int i = 0; i < 2; ++i) {
            int idx = j + i * NTHR;
            float mv = msa[idx];
            xcb[idx] = mv * xs[idx] + (1.f - mv) * xh[idx];
        }
        __syncthreads();

        // ---- phase 4: z_h = x_c@Wf.T + bf (2 rows per thread) ----
        {
            const int n = j & 127, q = j >> 7;            // q in 0..3
            u64 a0 = dup2(bf_[n]);
            #pragma unroll 8
            for (int k = 0; k < DD; ++k) {
                u64 wp = dup2(wt[OFF_WF + k * DD + n]);
                const u64* ap = (const u64*)&xcb[k * 8 + q * 2];
                a0 = ffma2(ap[0], wp, a0);
            }
            float v0, v1; unpk(a0, v0, v1);
            zh[n * 8 + q * 2 + 0] = v0;
            zh[n * 8 + q * 2 + 1] = v1;
        }
        __syncthreads();

        // ---- phase 5: c_h, c_c; write imputation + fp16 c_c for gates ----
        {
            const int base0 = rowbase * (TT * DD) + t * DD;
            #pragma unroll
            for (int i = 0; i < 2; ++i) {
                int idx2 = j + i * NTHR;
                int r = idx2 >> 7, k = idx2 & 127;
                int si = k * 8 + r;
                float a = al[si], zv = zh[si], xhv = xh[si], mv = msa[si], xv = xs[si];
                float ch = a * zv + (1.f - a) * xhv;
                float cc = mv * xv + (1.f - mv) * ch;
                inpH[r * INPH_PITCH + k] = __float2half(cc);
                out_imp[base0 + r * (TT * DD) + k] = cc;
            }
        }
        __syncthreads();

        // ---- phase 6: gates via tensor-core mma.sync (per-warp 64-col slice) ----
        {
            const int w = j >> 5, tl = j & 31;
            const int g = tl >> 2, c4 = tl & 3;
            float acc[8][2];
            #pragma unroll
            for (int u = 0; u < 8; ++u) { acc[u][0] = 0.f; acc[u][1] = 0.f; }
            float d2 = 0.f, d3 = 0.f;   // discarded rows 8-15
            const uint4* fragbase = (const uint4*)g_wtb_u + (size_t)w * 32 * 32 * 4;
            const __half* arow = inpH + g * INPH_PITCH + c4 * 2;
            #pragma unroll 4
            for (int s = 0; s < 32; ++s) {
                uint32_t a0 = *(const uint32_t*)(arow + s * 16);
                uint32_t a2 = *(const uint32_t*)(arow + s * 16 + 8);
                const uint4* wp = fragbase + (s * 32 + tl) * 4;
                uint4 q0 = wp[0], q1 = wp[1], q2 = wp[2], q3 = wp[3];
                mma1(acc[0][0], acc[0][1], d2, d3, a0, a2, q0.x, q0.y);
                mma1(acc[1][0], acc[1][1], d2, d3, a0, a2, q0.z, q0.w);
                mma1(acc[2][0], acc[2][1], d2, d3, a0, a2, q1.x, q1.y);
                mma1(acc[3][0], acc[3][1], d2, d3, a0, a2, q1.z, q1.w);
                mma1(acc[4][0], acc[4][1], d2, d3, a0, a2, q2.x, q2.y);
                mma1(acc[5][0], acc[5][1], d2, d3, a0, a2, q2.z, q2.w);
                mma1(acc[6][0], acc[6][1], d2, d3, a0, a2, q3.x, q3.y);
                mma1(acc[7][0], acc[7][1], d2, d3, a0, a2, q3.z, q3.w);
            }
            #pragma unroll
            for (int u = 0; u < 8; ++u) {
                int n0 = w * 64 + u * 8 + c4 * 2;
                gt[n0 * 8 + g]       = acc[u][0] + g_gb[n0];
                gt[(n0 + 1) * 8 + g] = acc[u][1] + g_gb[n0 + 1];
            }
        }
        __syncthreads();

        // ---- phase 7: LSTM cell update (2 threads per h-column, 4 rows each) ----
        {
            const int n = j & 255, half = j >> 8;
            #pragma unroll
            for (int r0 = 0; r0 < 4; ++r0) {
                int r = half * 4 + r0;
                float ig = sigf(gt[n * 8 + r]);
                float fg = sigf(gt[(n + HH) * 8 + r]);
                float gg = tanh_fast(gt[(n + 2 * HH) * 8 + r]);
                float og = sigf(gt[(n + 3 * HH) * 8 + r]);
                float cn = fg * cs[n * 8 + r] + ig * gg;
                cs[n * 8 + r] = cn;
                hs[n * 8 + r] = og * tanh_fast(cn);
            }
        }
        __syncthreads();
    }

    // ---- final: y_h = h@Wo.T + bo ----
    if (j < NROWS * CCLS) {
        int r = j >> 1, cl = j & 1;
        float acc = bo[cl];
        #pragma unroll 8
        for (int k = 0; k < HH; ++k) acc += hs[k * 8 + r] * Wo[cl * HH + k];
        out[(rowbase + r) * CCLS + cl] = acc;
    }
}

extern "C" void kernel_launch(void* const* d_in, const int* in_sizes, int n_in,
                              void* d_out, int out_size) {
    const float* values = (const float*)d_in[0];
    const int*   masks  = (const int*)  d_in[1];
    const float* deltas = (const float*)d_in[2];
    const float* Wdh = (const float*)d_in[3];
    const float* bdh = (const float*)d_in[4];
    const float* Wdx = (const float*)d_in[5];
    const float* bdx = (const float*)d_in[6];
    const float* Wh  = (const float*)d_in[7];
    const float* bh  = (const float*)d_in[8];
    const float* Wf  = (const float*)d_in[9];
    const float* bf_ = (const float*)d_in[10];
    const float* Wc  = (const float*)d_in[11];
    const float* bc  = (const float*)d_in[12];
    const float* Wih = (const float*)d_in[13];
    const float* bih = (const float*)d_in[14];
    const float* Whh = (const float*)d_in[15];
    const float* bhh = (const float*)d_in[16];
    const float* Wo  = (const float*)d_in[17];
    const float* bo  = (const float*)d_in[18];
    float* out = (float*)d_out;

    prep_kernel<<<(PREP_TOTAL + 255) / 256, 256>>>(Wdh, Wdx, Wh, Wf, Wc, Wih, Whh, bih, bhh);

    // smem: 22528 floats (90112 B) + inpH 8*520 halves (8320 B) = 98432 B
    size_t smem_bytes = 22528 * sizeof(float) + 8 * INPH_PITCH * sizeof(__half);
    cudaFuncSetAttribute(rits_kernel, cudaFuncAttributeMaxDynamicSharedMemorySize,
                         (int)smem_bytes);
    rits_kernel<<<NCTA, NTHR, smem_bytes>>>(values, masks, deltas,
                                            bdh, bdx, bh, bf_, bc,
                                            Wo, bo, out);
}

// round 7
// speedup vs baseline: 3.8916x; 2.4951x over previous
#include <cuda_runtime.h>
#include <cuda_bf16.h>
#include <cuda_fp16.h>
#include <cstdint>

// Problem dims
#define BB 1024
#define TT 512
#define DD 128
#define HH 256
#define CCLS 2
#define NROWS 8
#define NCTA (BB / NROWS)   // 128 CTAs
#define NTHR 512

// ---- fragment-packed fp16 weights (device global; no allocations allowed) ----
// Gates [0, 262144) u32, coalesced layout:
//   i = ((((w*32 + s)*4 + q)*32 + t)*4 + e),  u = q*2 + (e>>1), j2 = e&1
//   k0 = s*16 + (t&3)*2 + j2*8,  n = w*64 + u*8 + (t>>2)
//   val = half2(W[k0][n], W[k0+1][n]),  W[k][n] = k<256 ? Wih[n][k] : Whh[n][k-256]
// Small GEMM fragments (uint2 per (lane,tile,step)):
//   G1 (gamma_h|gamma_x: K=128, N=384=Wdh(256)|Wdx(128)):  i=((w*8+s)*3+uu)*64 + t*2 + j2
//   G2a (x_h: K=256,N=128, warps 0-7):  i=((w*16+s)*2+uu)*64 + t*2 + j2
//   G2b (alpha: K=256,N=128, warps 8-15): same with w-8
//   G3 (z_h: K=128,N=128): i=(w*8+s)*64 + t*2 + j2
#define SMG1  262144
#define SMG2A 286720
#define SMG2B 303104
#define SMG3  319488
#define WTB_TOTAL 327680
__device__ uint32_t g_wtb_u[WTB_TOTAL];
// Combined gate bias bih+bhh
__device__ float g_gb[4 * HH];

__device__ __forceinline__ float sigf(float x) { return 1.f / (1.f + __expf(-x)); }
__device__ __forceinline__ float tanh_fast(float x) { return 2.f / (1.f + __expf(-2.f * x)) - 1.f; }

// m16n8k16 HMMA; A rows 8-15 zero, c2/c3 discarded.
__device__ __forceinline__ void mma1(float& c0, float& c1, float& c2, float& c3,
                                     uint32_t a0, uint32_t a2, uint32_t b0, uint32_t b1) {
    asm volatile(
        "mma.sync.aligned.m16n8k16.row.col.f32.f16.f16.f32 "
        "{%0,%1,%2,%3}, {%4,%5,%6,%7}, {%8,%9}, {%0,%1,%2,%3};"
        : "+f"(c0), "+f"(c1), "+f"(c2), "+f"(c3)
        : "r"(a0), "r"(0u), "r"(a2), "r"(0u), "r"(b0), "r"(b1));
}

__device__ __forceinline__ uint32_t pack_pair(float lo, float hi) {
    uint32_t l = __half_as_ushort(__float2half_rn(lo));
    uint32_t h = __half_as_ushort(__float2half_rn(hi));
    return l | (h << 16);
}

// ---- fused prologue: all fragment packing + bias combine, ONE launch ----
#define PREP_TOTAL (WTB_TOTAL + 1024)
__global__ void prep_kernel(const float* __restrict__ Wdh, const float* __restrict__ Wdx,
                            const float* __restrict__ Wh,  const float* __restrict__ Wf,
                            const float* __restrict__ Wc,  const float* __restrict__ Wih,
                            const float* __restrict__ Whh, const float* __restrict__ bih,
                            const float* __restrict__ bhh) {
    int idx = blockIdx.x * blockDim.x + threadIdx.x;
    if (idx >= PREP_TOTAL) return;
    if (idx < 262144) {                    // gates, coalesced fragment layout
        int e = idx & 3, t = (idx >> 2) & 31, q = (idx >> 7) & 3;
        int s = (idx >> 9) & 31, w = (idx >> 14) & 15;
        int u = q * 2 + (e >> 1), j2 = e & 1;
        int k0 = s * 16 + (t & 3) * 2 + j2 * 8;
        int n  = w * 64 + u * 8 + (t >> 2);
        float lo, hi;
        if (k0 < 256) { lo = Wih[n * 256 + k0];       hi = Wih[n * 256 + k0 + 1]; }
        else          { lo = Whh[n * 256 + k0 - 256]; hi = Whh[n * 256 + k0 - 255]; }
        g_wtb_u[idx] = pack_pair(lo, hi);
    } else if (idx < SMG2A) {              // G1
        int i = idx - SMG1;
        int j2 = i & 1, t = (i >> 1) & 31;
        int rest = i >> 6, uu = rest % 3, ws = rest / 3;
        int s = ws & 7, w = ws >> 3;
        int tile = w * 3 + uu;
        int n = tile * 8 + (t >> 2);
        int k0 = s * 16 + (t & 3) * 2 + j2 * 8;
        float lo, hi;
        if (n < 256) { lo = Wdh[n * 128 + k0]; hi = Wdh[n * 128 + k0 + 1]; }
        else { int n2 = n - 256; lo = Wdx[n2 * 128 + k0]; hi = Wdx[n2 * 128 + k0 + 1]; }
        g_wtb_u[idx] = pack_pair(lo, hi);
    } else if (idx < SMG2B) {              // G2a: Wh
        int i = idx - SMG2A;
        int j2 = i & 1, t = (i >> 1) & 31;
        int rest = i >> 6, uu = rest & 1, ws = rest >> 1;
        int s = ws & 15, w = ws >> 4;
        int n = (w * 2 + uu) * 8 + (t >> 2);
        int k0 = s * 16 + (t & 3) * 2 + j2 * 8;
        g_wtb_u[idx] = pack_pair(Wh[n * 256 + k0], Wh[n * 256 + k0 + 1]);
    } else if (idx < SMG3) {               // G2b: Wc (input = gx || m)
        int i = idx - SMG2B;
        int j2 = i & 1, t = (i >> 1) & 31;
        int rest = i >> 6, uu = rest & 1, ws = rest >> 1;
        int s = ws & 15, w = ws >> 4;
        int n = (w * 2 + uu) * 8 + (t >> 2);
        int k0 = s * 16 + (t & 3) * 2 + j2 * 8;
        g_wtb_u[idx] = pack_pair(Wc[n * 256 + k0], Wc[n * 256 + k0 + 1]);
    } else if (idx < WTB_TOTAL) {          // G3: Wf
        int i = idx - SMG3;
        int j2 = i & 1, t = (i >> 1) & 31;
        int rest = i >> 6, s = rest & 7, w = rest >> 3;
        int n = w * 8 + (t >> 2);
        int k0 = s * 16 + (t & 3) * 2 + j2 * 8;
        g_wtb_u[idx] = pack_pair(Wf[n * 128 + k0], Wf[n * 128 + k0 + 1]);
    } else {                               // combined gate bias
        int i = idx - WTB_TOTAL;
        g_gb[i] = bih[i] + bhh[i];
    }
}

// ---- persistent RITS scan. Each CTA owns 8 batch rows for all 512 steps. ----
// fp16 activation shadow actH[8][P]: per row r:
//   [0:128) c_c | [128:256) m | [256:512) hd | [512:640) gx | [640:768) m copy | [768:896) dsa | [896:1024) x_c
#define PH 1032   // pitch in halves (2064 B: 516 mod 32 = 4 -> conflict-free 8x4 LDS pattern)
__global__ void __launch_bounds__(NTHR, 1) rits_kernel(
    const float* __restrict__ values, const int* __restrict__ masks, const float* __restrict__ deltas,
    const float* __restrict__ bdh, const float* __restrict__ bdx,
    const float* __restrict__ bh,  const float* __restrict__ bf_,
    const float* __restrict__ bc,
    const float* __restrict__ Wo,  const float* __restrict__ bo,
    float* __restrict__ out)
{
    extern __shared__ float smem[];
    float* hs  = smem;            // [H*8]
    float* cs  = hs  + 2048;      // [H*8]
    float* xs  = cs  + 2048;      // [D*8]
    float* msa = xs  + 1024;      // [D*8]
    float* xh  = msa + 1024;      // [D*8]
    float* al  = xh  + 1024;      // [D*8]
    float* zh  = al  + 1024;      // [D*8]
    float* gt  = zh  + 1024;      // [4H*8]
    __half* actH = (__half*)(gt + 8192);  // [8][PH]

    const int j = threadIdx.x;
    const int w = j >> 5, tl = j & 31;
    const int rr = tl >> 2, c4 = tl & 3;
    const int rowbase = blockIdx.x * NROWS;
    float* out_imp = out + BB * CCLS;

    for (int i = j; i < 2048; i += NTHR) { hs[i] = 0.f; cs[i] = 0.f; }

    // input prefetch registers (double-buffer in regs across steps)
    float pv[2], pm[2], pd[2];
    {
        const int base0 = rowbase * (TT * DD);
        #pragma unroll
        for (int i = 0; i < 2; ++i) {
            int idx = j + i * NTHR;
            int r = idx >> 7, k = idx & 127;
            int g = base0 + r * (TT * DD) + k;
            pv[i] = values[g]; pm[i] = (float)masks[g]; pd[i] = deltas[g];
        }
    }
    __syncthreads();

    for (int t = 0; t < TT; ++t) {
        // ---- phase 1: commit prefetched x, m, d ----
        #pragma unroll
        for (int i = 0; i < 2; ++i) {
            int idx = j + i * NTHR;
            int r = idx >> 7, k = idx & 127;
            int si = k * 8 + r;
            xs[si] = pv[i]; msa[si] = pm[i];
            __half mh = __float2half(pm[i]);
            actH[r * PH + 128 + k] = mh;          // m (gates)
            actH[r * PH + 640 + k] = mh;          // m (alpha)
            actH[r * PH + 768 + k] = __float2half(pd[i]);  // dsa
        }
        __syncthreads();

        // issue next step's input loads
        if (t + 1 < TT) {
            const int base0 = rowbase * (TT * DD) + (t + 1) * DD;
            #pragma unroll
            for (int i = 0; i < 2; ++i) {
                int idx = j + i * NTHR;
                int r = idx >> 7, k = idx & 127;
                int g = base0 + r * (TT * DD) + k;
                pv[i] = values[g]; pm[i] = (float)masks[g]; pd[i] = deltas[g];
            }
        }

        // ---- phase 2 (G1): gamma_h | gamma_x via HMMA; K=128, N=384; 3 tiles/warp ----
        {
            float acc[3][2]; float d2 = 0.f, d3 = 0.f;
            #pragma unroll
            for (int uu = 0; uu < 3; ++uu) { acc[uu][0] = 0.f; acc[uu][1] = 0.f; }
            const __half* arow = actH + rr * PH + 768 + c4 * 2;
            const uint2* fb = (const uint2*)(g_wtb_u + SMG1);
            #pragma unroll 2
            for (int s = 0; s < 8; ++s) {
                uint32_t a0 = *(const uint32_t*)(arow + s * 16);
                uint32_t a2 = *(const uint32_t*)(arow + s * 16 + 8);
                const uint2* wp = fb + ((w * 8 + s) * 3) * 32 + tl;
                uint2 b0 = wp[0], b1 = wp[32], b2 = wp[64];
                mma1(acc[0][0], acc[0][1], d2, d3, a0, a2, b0.x, b0.y);
                mma1(acc[1][0], acc[1][1], d2, d3, a0, a2, b1.x, b1.y);
                mma1(acc[2][0], acc[2][1], d2, d3, a0, a2, b2.x, b2.y);
            }
            #pragma unroll
            for (int uu = 0; uu < 3; ++uu) {
                int tile = w * 3 + uu;
                int n0 = tile * 8 + c4 * 2;
                #pragma unroll
                for (int c = 0; c < 2; ++c) {
                    int n = n0 + c;
                    if (tile < 32) {
                        float gam = __expf(-fmaxf(acc[uu][c] + bdh[n], 0.f));
                        float hv = hs[n * 8 + rr] * gam;
                        actH[rr * PH + 256 + n] = __float2half(hv);
                    } else {
                        int n2 = n - 256;
                        float gxv = __expf(-fmaxf(acc[uu][c] + bdx[n2], 0.f));
                        actH[rr * PH + 512 + n2] = __float2half(gxv);
                    }
                }
            }
        }
        __syncthreads();

        // ---- phase 3 (G2): x_h (warps 0-7, A=hd) | alpha (warps 8-15, A=gx||m) ----
        {
            float acc[2][2]; float d2 = 0.f, d3 = 0.f;
            acc[0][0] = acc[0][1] = acc[1][0] = acc[1][1] = 0.f;
            const bool isA = (w < 8);
            const int wl = isA ? w : (w - 8);
            const __half* arow = actH + rr * PH + (isA ? 256 : 512) + c4 * 2;
            const uint2* fb = (const uint2*)(g_wtb_u + (isA ? SMG2A : SMG2B));
            #pragma unroll 4
            for (int s = 0; s < 16; ++s) {
                uint32_t a0 = *(const uint32_t*)(arow + s * 16);
                uint32_t a2 = *(const uint32_t*)(arow + s * 16 + 8);
                const uint2* wp = fb + ((wl * 16 + s) * 2) * 32 + tl;
                uint2 b0 = wp[0], b1 = wp[32];
                mma1(acc[0][0], acc[0][1], d2, d3, a0, a2, b0.x, b0.y);
                mma1(acc[1][0], acc[1][1], d2, d3, a0, a2, b1.x, b1.y);
            }
            #pragma unroll
            for (int uu = 0; uu < 2; ++uu) {
                int n0 = (wl * 2 + uu) * 8 + c4 * 2;
                #pragma unroll
                for (int c = 0; c < 2; ++c) {
                    int n = n0 + c;
                    if (isA) xh[n * 8 + rr] = acc[uu][c] + bh[n];
                    else     al[n * 8 + rr] = acc[uu][c] + bc[n];
                }
            }
        }
        __syncthreads();

        // ---- phase 3.5: x_c = m*x + (1-m)*x_h -> fp16 shadow ----
        #pragma unroll
        for (int i = 0; i < 2; ++i) {
            int idx = j + i * NTHR;
            float mv = msa[idx];
            float xc = mv * xs[idx] + (1.f - mv) * xh[idx];
            int k = idx >> 3, r = idx & 7;
            actH[r * PH + 896 + k] = __float2half(xc);
        }
        __syncthreads();

        // ---- phase 4 (G3): z_h via HMMA; K=128, N=128; 1 tile/warp ----
        {
            float acc0 = 0.f, acc1 = 0.f, d2 = 0.f, d3 = 0.f;
            const __half* arow = actH + rr * PH + 896 + c4 * 2;
            const uint2* fb = (const uint2*)(g_wtb_u + SMG3);
            #pragma unroll 2
            for (int s = 0; s < 8; ++s) {
                uint32_t a0 = *(const uint32_t*)(arow + s * 16);
                uint32_t a2 = *(const uint32_t*)(arow + s * 16 + 8);
                uint2 b0 = fb[(w * 8 + s) * 32 + tl];
                mma1(acc0, acc1, d2, d3, a0, a2, b0.x, b0.y);
            }
            int n0 = w * 8 + c4 * 2;
            zh[n0 * 8 + rr]       = acc0 + bf_[n0];
            zh[(n0 + 1) * 8 + rr] = acc1 + bf_[n0 + 1];
        }
        __syncthreads();

        // ---- phase 5: c_h, c_c; write imputation + fp16 c_c ----
        {
            const int base0 = rowbase * (TT * DD) + t * DD;
            #pragma unroll
            for (int i = 0; i < 2; ++i) {
                int idx2 = j + i * NTHR;
                int r = idx2 >> 7, k = idx2 & 127;
                int si = k * 8 + r;
                float a = al[si], zv = zh[si], xhv = xh[si], mv = msa[si], xv = xs[si];
                float ch = a * zv + (1.f - a) * xhv;
                float cc = mv * xv + (1.f - mv) * ch;
                actH[r * PH + k] = __float2half(cc);
                out_imp[base0 + r * (TT * DD) + k] = cc;
            }
        }
        __syncthreads();

        // ---- phase 6: gates via HMMA (per-warp 64-col slice, coalesced frags) ----
        {
            float acc[8][2];
            #pragma unroll
            for (int u = 0; u < 8; ++u) { acc[u][0] = 0.f; acc[u][1] = 0.f; }
            float d2 = 0.f, d3 = 0.f;
            const uint4* fragbase = (const uint4*)g_wtb_u + (size_t)w * 4096;
            const __half* arow = actH + rr * PH + c4 * 2;
            #pragma unroll 4
            for (int s = 0; s < 32; ++s) {
                uint32_t a0 = *(const uint32_t*)(arow + s * 16);
                uint32_t a2 = *(const uint32_t*)(arow + s * 16 + 8);
                const uint4* wp = fragbase + s * 128 + tl;
                uint4 q0 = wp[0], q1 = wp[32], q2 = wp[64], q3 = wp[96];
                mma1(acc[0][0], acc[0][1], d2, d3, a0, a2, q0.x, q0.y);
                mma1(acc[1][0], acc[1][1], d2, d3, a0, a2, q0.z, q0.w);
                mma1(acc[2][0], acc[2][1], d2, d3, a0, a2, q1.x, q1.y);
                mma1(acc[3][0], acc[3][1], d2, d3, a0, a2, q1.z, q1.w);
                mma1(acc[4][0], acc[4][1], d2, d3, a0, a2, q2.x, q2.y);
                mma1(acc[5][0], acc[5][1], d2, d3, a0, a2, q2.z, q2.w);
                mma1(acc[6][0], acc[6][1], d2, d3, a0, a2, q3.x, q3.y);
                mma1(acc[7][0], acc[7][1], d2, d3, a0, a2, q3.z, q3.w);
            }
            #pragma unroll
            for (int u = 0; u < 8; ++u) {
                int n0 = w * 64 + u * 8 + c4 * 2;
                gt[n0 * 8 + rr]       = acc[u][0] + g_gb[n0];
                gt[(n0 + 1) * 8 + rr] = acc[u][1] + g_gb[n0 + 1];
            }
        }
        __syncthreads();

        // ---- phase 7: LSTM cell update (2 threads per h-column, 4 rows each) ----
        {
            const int n = j & 255, half = j >> 8;
            #pragma unroll
            for (int r0 = 0; r0 < 4; ++r0) {
                int r = half * 4 + r0;
                float ig = sigf(gt[n * 8 + r]);
                float fg = sigf(gt[(n + HH) * 8 + r]);
                float gg = tanh_fast(gt[(n + 2 * HH) * 8 + r]);
                float og = sigf(gt[(n + 3 * HH) * 8 + r]);
                float cn = fg * cs[n * 8 + r] + ig * gg;
                cs[n * 8 + r] = cn;
                hs[n * 8 + r] = og * tanh_fast(cn);
            }
        }
        __syncthreads();
    }

    // ---- final: y_h = h@Wo.T + bo ----
    if (j < NROWS * CCLS) {
        int r = j >> 1, cl = j & 1;
        float acc = bo[cl];
        #pragma unroll 8
        for (int k = 0; k < HH; ++k) acc += hs[k * 8 + r] * Wo[cl * HH + k];
        out[(rowbase + r) * CCLS + cl] = acc;
    }
}

extern "C" void kernel_launch(void* const* d_in, const int* in_sizes, int n_in,
                              void* d_out, int out_size) {
    const float* values = (const float*)d_in[0];
    const int*   masks  = (const int*)  d_in[1];
    const float* deltas = (const float*)d_in[2];
    const float* Wdh = (const float*)d_in[3];
    const float* bdh = (const float*)d_in[4];
    const float* Wdx = (const float*)d_in[5];
    const float* bdx = (const float*)d_in[6];
    const float* Wh  = (const float*)d_in[7];
    const float* bh  = (const float*)d_in[8];
    const float* Wf  = (const float*)d_in[9];
    const float* bf_ = (const float*)d_in[10];
    const float* Wc  = (const float*)d_in[11];
    const float* bc  = (const float*)d_in[12];
    const float* Wih = (const float*)d_in[13];
    const float* bih = (const float*)d_in[14];
    const float* Whh = (const float*)d_in[15];
    const float* bhh = (const float*)d_in[16];
    const float* Wo  = (const float*)d_in[17];
    const float* bo  = (const float*)d_in[18];
    float* out = (float*)d_out;

    prep_kernel<<<(PREP_TOTAL + 255) / 256, 256>>>(Wdh, Wdx, Wh, Wf, Wc, Wih, Whh, bih, bhh);

    // smem: 17408 floats (69632 B) + actH 8*1032 halves (16512 B) = 86144 B
    size_t smem_bytes = 17408 * sizeof(float) + 8 * PH * sizeof(__half);
    cudaFuncSetAttribute(rits_kernel, cudaFuncAttributeMaxDynamicSharedMemorySize,
                         (int)smem_bytes);
    rits_kernel<<<NCTA, NTHR, smem_bytes>>>(values, masks, deltas,
                                            bdh, bdx, bh, bf_, bc,
                                            Wo, bo, out);
}